// round 10
// baseline (speedup 1.0000x reference)
#include <cuda_runtime.h>
#include <cuda_bf16.h>
#include <math.h>

#define BB 4
#define CC 64
#define HH 128
#define WW 128
#define OO 64
#define NKK 9
#define QDIM 576
#define NPIX (BB*HH*WW)     // 65536

typedef unsigned int u32;

// ---- device scratch ----
__device__ float g_xT[BB*HH*WW*CC];             // NHWC x
__device__ float g_params[27*NPIX];             // planar [co][pix]
__device__ uint4 g_wbF [NKK*4*4*32];            // main W bf16-hi fragments [kk][ks][np][lane]
__device__ uint4 g_wbFL[NKK*4*4*32];            // main W bf16-lo fragments
__device__ uint4 g_wpgF [NKK*4*2*32];           // pg W bf16-hi fragments [kk][ks][np][lane]
__device__ uint4 g_wpgFL[NKK*4*2*32];           // pg W bf16-lo fragments

__device__ __forceinline__ u32 smem_u32(const void* p) {
    u32 a;
    asm("{ .reg .u64 t; cvta.to.shared.u64 t, %1; cvt.u32.u64 %0, t; }" : "=r"(a) : "l"(p));
    return a;
}

#define LDSM4(r0, r1, r2, r3, addr) \
    asm volatile("ldmatrix.sync.aligned.m8n8.x4.shared.b16 {%0,%1,%2,%3},[%4];" \
        : "=r"(r0), "=r"(r1), "=r"(r2), "=r"(r3) : "r"(addr))

__device__ __forceinline__ void mma16816(float* d, u32 a0, u32 a1, u32 a2, u32 a3,
                                         u32 b0, u32 b1) {
    asm volatile(
        "mma.sync.aligned.m16n8k16.row.col.f32.bf16.bf16.f32 "
        "{%0,%1,%2,%3},{%4,%5,%6,%7},{%8,%9},{%0,%1,%2,%3};"
        : "+f"(d[0]), "+f"(d[1]), "+f"(d[2]), "+f"(d[3])
        : "r"(a0), "r"(a1), "r"(a2), "r"(a3), "r"(b0), "r"(b1));
}

__device__ __forceinline__ void split_store(unsigned char* dst_hi, unsigned char* dst_lo,
                                            float v0, float v1, float v2, float v3) {
    __nv_bfloat162 h01 = __floats2bfloat162_rn(v0, v1);
    __nv_bfloat162 h23 = __floats2bfloat162_rn(v2, v3);
    float l0 = v0 - __bfloat162float(h01.x);
    float l1 = v1 - __bfloat162float(h01.y);
    float l2 = v2 - __bfloat162float(h23.x);
    float l3 = v3 - __bfloat162float(h23.y);
    __nv_bfloat162 L01 = __floats2bfloat162_rn(l0, l1);
    __nv_bfloat162 L23 = __floats2bfloat162_rn(l2, l3);
    *(uint2*)dst_hi = make_uint2(*(u32*)&h01, *(u32*)&h23);
    *(uint2*)dst_lo = make_uint2(*(u32*)&L01, *(u32*)&L23);
}

// hi/lo bf16x2 words for two consecutive-c weights (v0 -> low half)
__device__ __forceinline__ void split_pack(float v0, float v1, u32& hi, u32& lo) {
    __nv_bfloat162 h = __floats2bfloat162_rn(v0, v1);
    float l0 = v0 - __bfloat162float(h.x);
    float l1 = v1 - __bfloat162float(h.y);
    __nv_bfloat162 L = __floats2bfloat162_rn(l0, l1);
    hi = *(u32*)&h;
    lo = *(u32*)&L;
}

// ============================================================
// Kernel 0: x NCHW -> NHWC
// ============================================================
__global__ void k_transpose_x(const float* __restrict__ x) {
    __shared__ float tile[64][129];
    int bh = blockIdx.x;
    int b = bh >> 7, h = bh & 127;
    int t = threadIdx.x;
    for (int i = t; i < 64 * 128; i += 256) {
        int c = i >> 7, w = i & 127;
        tile[c][w] = x[((size_t)(b * CC + c) * HH + h) * WW + w];
    }
    __syncthreads();
    for (int i = t; i < 64 * 128; i += 256) {
        int w = i >> 6, c = i & 63;
        g_xT[((size_t)bh * WW + w) * CC + c] = tile[c][w];
    }
}

// ============================================================
// Kernel 1: main weight fragments. B[o][c] per tap; fragment word map
// (validated LDSM-equivalent): lane l, np: o1=np*16+(l>>2), o2=o1+8,
// c0=ks*16+(l&3)*2, c1=c0+8 -> uint4{w(o1,c0),w(o1,c1),w(o2,c0),w(o2,c1)}
// ============================================================
__global__ void k_prep_wbF(const float* __restrict__ wgt) {
    int i = blockIdx.x * 256 + threadIdx.x;      // 4608
    if (i >= NKK * 4 * 4 * 32) return;
    int lane = i & 31;
    int np = (i >> 5) & 3;
    int ks = (i >> 7) & 3;
    int kk = i >> 9;
    int o1 = np * 16 + (lane >> 2);
    int o2 = o1 + 8;
    int c0 = ks * 16 + (lane & 3) * 2;
    int c1 = c0 + 8;
    uint4 fh, fl;
    split_pack(wgt[(o1 * CC + c0) * 9 + kk], wgt[(o1 * CC + c0 + 1) * 9 + kk], fh.x, fl.x);
    split_pack(wgt[(o1 * CC + c1) * 9 + kk], wgt[(o1 * CC + c1 + 1) * 9 + kk], fh.y, fl.y);
    split_pack(wgt[(o2 * CC + c0) * 9 + kk], wgt[(o2 * CC + c0 + 1) * 9 + kk], fh.z, fl.z);
    split_pack(wgt[(o2 * CC + c1) * 9 + kk], wgt[(o2 * CC + c1 + 1) * 9 + kk], fh.w, fl.w);
    g_wbF[i] = fh;
    g_wbFL[i] = fl;
}

// pg weights: co (0..26, pad 32), w = pgw[co*576 + c*9 + kk]
__global__ void k_prep_wpgF(const float* __restrict__ pgw) {
    int i = blockIdx.x * 256 + threadIdx.x;      // 2304
    if (i >= NKK * 4 * 2 * 32) return;
    int lane = i & 31;
    int np = (i >> 5) & 1;
    int ks = (i >> 6) & 3;
    int kk = i >> 8;
    int o1 = np * 16 + (lane >> 2);
    int o2 = o1 + 8;
    int c0 = ks * 16 + (lane & 3) * 2;
    int c1 = c0 + 8;
    uint4 fh, fl;
    float w00 = (o1 < 27) ? pgw[o1 * QDIM + c0 * 9 + kk] : 0.f;
    float w01 = (o1 < 27) ? pgw[o1 * QDIM + (c0 + 1) * 9 + kk] : 0.f;
    float w10 = (o1 < 27) ? pgw[o1 * QDIM + c1 * 9 + kk] : 0.f;
    float w11 = (o1 < 27) ? pgw[o1 * QDIM + (c1 + 1) * 9 + kk] : 0.f;
    float w20 = (o2 < 27) ? pgw[o2 * QDIM + c0 * 9 + kk] : 0.f;
    float w21 = (o2 < 27) ? pgw[o2 * QDIM + (c0 + 1) * 9 + kk] : 0.f;
    float w30 = (o2 < 27) ? pgw[o2 * QDIM + c1 * 9 + kk] : 0.f;
    float w31 = (o2 < 27) ? pgw[o2 * QDIM + (c1 + 1) * 9 + kk] : 0.f;
    split_pack(w00, w01, fh.x, fl.x);
    split_pack(w10, w11, fh.y, fl.y);
    split_pack(w20, w21, fh.z, fl.z);
    split_pack(w30, w31, fh.w, fl.w);
    g_wpgF[i] = fh;
    g_wpgFL[i] = fl;
}

// ============================================================
// MMA constants
// ============================================================
#define APITCH 72                    // bf16/row (144 B)
#define ROWB (APITCH*2)              // 144
#define A_BYTES (64 * ROWB)          // 9216
#define DPITCH 68
#define BLOB_BYTES (2 * A_BYTES)     // 18432 (A hi+lo; epilogue reuses)

// ============================================================
// Kernel 2: offset/mask conv. block = 64 px, 128 thr, 18.4 KB smem
// ============================================================
__global__ void __launch_bounds__(128) k_params(const float* __restrict__ pgb) {
    __shared__ __align__(16) unsigned char blob[BLOB_BYTES];
    u32 S = smem_u32(blob);
    int t = threadIdx.x;
    int lane = t & 31;
    int warp = t >> 5;
    int blk = blockIdx.x;            // 1024
    int wb = (blk & 1) * 64;
    int bh = blk >> 1;
    int b = bh >> 7, h = bh & 127;

    const float* xb = &g_xT[(size_t)b * HH * WW * CC];

    float acc[4][4];
#pragma unroll
    for (int j = 0; j < 4; j++)
#pragma unroll
        for (int r = 0; r < 4; r++) acc[j][r] = 0.f;

    u32 aRow = (u32)((warp * 16 + (lane & 15)) * ROWB) + (u32)((lane >> 4) * 16);
    int px = t >> 1;
    int half = t & 1;

#pragma unroll 1
    for (int kk = 0; kk < NKK; kk++) {
        __syncthreads();             // prev MMA reads done
        // ---- stage A: shifted patch, this thread: (px, 32 c) ----
        {
            int dh = kk / 3 - 1, dw = kk % 3 - 1;
            int hh = h + dh;
            int gw = wb + px + dw;
            bool ok = (hh >= 0 && hh < HH && gw >= 0 && gw < WW);
            const float4* src = (const float4*)(xb +
                ((size_t)(ok ? hh : 0) * WW + (ok ? gw : 0)) * CC + half * 32);
            unsigned char* dh_ = blob + px * ROWB + half * 64;
            unsigned char* dl_ = dh_ + A_BYTES;
#pragma unroll
            for (int i = 0; i < 8; i++) {
                float4 g = make_float4(0.f, 0.f, 0.f, 0.f);
                if (ok) g = __ldg(src + i);
                split_store(dh_ + i * 8, dl_ + i * 8, g.x, g.y, g.z, g.w);
            }
        }
        __syncthreads();
        // ---- MMA: B fragments straight from global (L1-resident) ----
#pragma unroll
        for (int ks = 0; ks < 4; ks++) {
            u32 aa = S + aRow + ks * 32;
            u32 ah0, ah1, ah2, ah3, al0, al1, al2, al3;
            LDSM4(ah0, ah1, ah2, ah3, aa);
            LDSM4(al0, al1, al2, al3, aa + A_BYTES);
#pragma unroll
            for (int np = 0; np < 2; np++) {
                int fi = ((kk * 4 + ks) * 2 + np) * 32 + lane;
                uint4 fh = __ldg(&g_wpgF[fi]);
                uint4 fl = __ldg(&g_wpgFL[fi]);
                mma16816(acc[np * 2 + 0], ah0, ah1, ah2, ah3, fh.x, fh.y);
                mma16816(acc[np * 2 + 1], ah0, ah1, ah2, ah3, fh.z, fh.w);
                mma16816(acc[np * 2 + 0], ah0, ah1, ah2, ah3, fl.x, fl.y);
                mma16816(acc[np * 2 + 1], ah0, ah1, ah2, ah3, fl.z, fl.w);
                mma16816(acc[np * 2 + 0], al0, al1, al2, al3, fh.x, fh.y);
                mma16816(acc[np * 2 + 1], al0, al1, al2, al3, fh.z, fh.w);
            }
        }
    }

    // ---- epilogue: stage sD[32co][68px], planar coalesced write ----
    __syncthreads();
    float* sD = (float*)blob;
    {
        int px0 = warp * 16 + (lane >> 2);
#pragma unroll
        for (int j = 0; j < 4; j++) {
            int co = j * 8 + 2 * (lane & 3);
            sD[co * DPITCH + px0]           = acc[j][0];
            sD[(co + 1) * DPITCH + px0]     = acc[j][1];
            sD[co * DPITCH + px0 + 8]       = acc[j][2];
            sD[(co + 1) * DPITCH + px0 + 8] = acc[j][3];
        }
    }
    __syncthreads();
#pragma unroll
    for (int i = 0; i < 14; i++) {
        int idx = i * 128 + t;               // 27*64 = 1728
        if (idx < 1728) {
            int co = idx >> 6;
            int pxx = idx & 63;
            g_params[(size_t)co * NPIX + (size_t)bh * WW + wb + pxx] =
                sD[co * DPITCH + pxx] + __ldg(&pgb[co]);
        }
    }
}

// ============================================================
// Kernel 3: fused gather + MMA. block = 64 px, 128 thr, 18.4 KB smem
// ============================================================
__global__ void __launch_bounds__(128) k_main(const float* __restrict__ bias,
                                              float* __restrict__ out) {
    __shared__ __align__(16) unsigned char blob[BLOB_BYTES];
    u32 S = smem_u32(blob);
    int t = threadIdx.x;
    int lane = t & 31;
    int warp = t >> 5;
    int blk = blockIdx.x;
    int wb = (blk & 1) * 64;
    int bh = blk >> 1;
    int b = bh >> 7, h = bh & 127;

    const float* xb = &g_xT[(size_t)b * HH * WW * CC];

    float acc[8][4];
#pragma unroll
    for (int j = 0; j < 8; j++)
#pragma unroll
        for (int r = 0; r < 4; r++) acc[j][r] = 0.f;

    u32 aRow = (u32)((warp * 16 + (lane & 15)) * ROWB) + (u32)((lane >> 4) * 16);
    int px = t >> 1;
    int half = t & 1;
    int w = wb + px;
    size_t pixi = (size_t)bh * WW + w;

#pragma unroll 1
    for (int kk = 0; kk < NKK; kk++) {
        __syncthreads();             // prev MMA reads done
        // ---- params (per-thread, duplicated across halves) + gather ----
        {
            float dy = __ldg(&g_params[(size_t)(2 * kk) * NPIX + pixi]);
            float dx = __ldg(&g_params[(size_t)(2 * kk + 1) * NPIX + pixi]);
            float m  = __ldg(&g_params[(size_t)(18 + kk) * NPIX + pixi]);
            float mask = 1.f / (1.f + expf(-m));
            float ys = (float)(h - 1 + kk / 3) + dy;
            float xs = (float)(w - 1 + kk % 3) + dx;
            float y0f = floorf(ys), x0f = floorf(xs);
            float ly = ys - y0f, lx = xs - x0f;
            int y0 = (int)y0f, x0 = (int)x0f;
            float vy0 = (y0 >= 0 && y0 < HH) ? 1.f : 0.f;
            float vy1 = (y0 + 1 >= 0 && y0 + 1 < HH) ? 1.f : 0.f;
            float vx0 = (x0 >= 0 && x0 < WW) ? 1.f : 0.f;
            float vx1 = (x0 + 1 >= 0 && x0 + 1 < WW) ? 1.f : 0.f;
            float w00 = (1.f - ly) * (1.f - lx) * mask * vy0 * vx0;
            float w01 = (1.f - ly) * lx         * mask * vy0 * vx1;
            float w10 = ly * (1.f - lx)         * mask * vy1 * vx0;
            float w11 = ly * lx                 * mask * vy1 * vx1;
            int r0  = min(max(y0, 0), HH - 1) * WW;
            int r1  = min(max(y0 + 1, 0), HH - 1) * WW;
            int x0c = min(max(x0, 0), WW - 1);
            int x1c = min(max(x0 + 1, 0), WW - 1);
            const float4* p00 = (const float4*)(xb + (size_t)(r0 + x0c) * CC + half * 32);
            const float4* p01 = (const float4*)(xb + (size_t)(r0 + x1c) * CC + half * 32);
            const float4* p10 = (const float4*)(xb + (size_t)(r1 + x0c) * CC + half * 32);
            const float4* p11 = (const float4*)(xb + (size_t)(r1 + x1c) * CC + half * 32);
            unsigned char* dh_ = blob + px * ROWB + half * 64;
            unsigned char* dl_ = dh_ + A_BYTES;
            float4 c0 = __ldg(p00), c1 = __ldg(p01), c2 = __ldg(p10), c3 = __ldg(p11);
#pragma unroll
            for (int i = 0; i < 8; i++) {
                float4 n0, n1, n2, n3;
                if (i < 7) {
                    n0 = __ldg(p00 + i + 1); n1 = __ldg(p01 + i + 1);
                    n2 = __ldg(p10 + i + 1); n3 = __ldg(p11 + i + 1);
                }
                float v0 = w00 * c0.x + w01 * c1.x + w10 * c2.x + w11 * c3.x;
                float v1 = w00 * c0.y + w01 * c1.y + w10 * c2.y + w11 * c3.y;
                float v2 = w00 * c0.z + w01 * c1.z + w10 * c2.z + w11 * c3.z;
                float v3 = w00 * c0.w + w01 * c1.w + w10 * c2.w + w11 * c3.w;
                split_store(dh_ + i * 8, dl_ + i * 8, v0, v1, v2, v3);
                if (i < 7) { c0 = n0; c1 = n1; c2 = n2; c3 = n3; }
            }
        }
        __syncthreads();
        // ---- MMA: B fragments from global ----
#pragma unroll
        for (int ks = 0; ks < 4; ks++) {
            u32 aa = S + aRow + ks * 32;
            u32 ah0, ah1, ah2, ah3, al0, al1, al2, al3;
            LDSM4(ah0, ah1, ah2, ah3, aa);
            LDSM4(al0, al1, al2, al3, aa + A_BYTES);
#pragma unroll
            for (int np = 0; np < 4; np++) {
                int fi = ((kk * 4 + ks) * 4 + np) * 32 + lane;
                uint4 fh = __ldg(&g_wbF[fi]);
                uint4 fl = __ldg(&g_wbFL[fi]);
                mma16816(acc[np * 2 + 0], ah0, ah1, ah2, ah3, fh.x, fh.y);
                mma16816(acc[np * 2 + 1], ah0, ah1, ah2, ah3, fh.z, fh.w);
                mma16816(acc[np * 2 + 0], ah0, ah1, ah2, ah3, fl.x, fl.y);
                mma16816(acc[np * 2 + 1], ah0, ah1, ah2, ah3, fl.z, fl.w);
                mma16816(acc[np * 2 + 0], al0, al1, al2, al3, fh.x, fh.y);
                mma16816(acc[np * 2 + 1], al0, al1, al2, al3, fh.z, fh.w);
            }
        }
    }

    // ---- epilogue ----
    __syncthreads();
    float* sD = (float*)blob;
    {
        int px0 = warp * 16 + (lane >> 2);
#pragma unroll
        for (int j = 0; j < 8; j++) {
            int o = j * 8 + 2 * (lane & 3);
            sD[o * DPITCH + px0]           = acc[j][0];
            sD[(o + 1) * DPITCH + px0]     = acc[j][1];
            sD[o * DPITCH + px0 + 8]       = acc[j][2];
            sD[(o + 1) * DPITCH + px0 + 8] = acc[j][3];
        }
    }
    __syncthreads();
    {
        int o = t >> 1;
        int hf = t & 1;
        float bv = __ldg(&bias[o]);
        size_t base = ((size_t)(b * OO + o) * HH + h) * WW + wb + hf * 32;
        const float* src = &sD[o * DPITCH + hf * 32];
#pragma unroll
        for (int i = 0; i < 8; i++) {
            float4 v = *(const float4*)&src[i * 4];
            v.x += bv; v.y += bv; v.z += bv; v.w += bv;
            *(float4*)&out[base + i * 4] = v;
        }
    }
}

// ============================================================
extern "C" void kernel_launch(void* const* d_in, const int* in_sizes, int n_in,
                              void* d_out, int out_size) {
    const float* x      = (const float*)d_in[0];
    const float* weight = (const float*)d_in[1];
    const float* bias   = (const float*)d_in[2];
    const float* pg_w   = (const float*)d_in[3];
    const float* pg_b   = (const float*)d_in[4];
    float* out = (float*)d_out;

    k_transpose_x<<<BB * HH, 256>>>(x);
    k_prep_wbF<<<(NKK * 4 * 4 * 32 + 255) / 256, 256>>>(weight);
    k_prep_wpgF<<<(NKK * 4 * 2 * 32 + 255) / 256, 256>>>(pg_w);
    k_params<<<BB * HH * 2, 128>>>(pg_b);
    k_main<<<BB * HH * 2, 128>>>(bias, out);
}

// round 11
// speedup vs baseline: 1.6796x; 1.6796x over previous
#include <cuda_runtime.h>
#include <cuda_bf16.h>
#include <math.h>

#define BB 4
#define CC 64
#define HH 128
#define WW 128
#define OO 64
#define NKK 9
#define QDIM 576
#define NPIX (BB*HH*WW)     // 65536

typedef unsigned int u32;

// ---- device scratch ----
__device__ float g_xT[BB*HH*WW*CC];             // NHWC x
__device__ float g_params[27*NPIX];             // planar [co][pix]
__device__ __nv_bfloat16 g_wbH[NKK*OO*CC];      // main weights bf16 hi, [kk][o][c]
__device__ __nv_bfloat16 g_wbL[NKK*OO*CC];      // main weights bf16 lo
__device__ __nv_bfloat16 g_wpgH[NKK*32*CC];     // pg weights bf16 hi, [kk][co32][c]
__device__ __nv_bfloat16 g_wpgL[NKK*32*CC];     // pg weights bf16 lo

__device__ __forceinline__ u32 smem_u32(const void* p) {
    u32 a;
    asm("{ .reg .u64 t; cvta.to.shared.u64 t, %1; cvt.u32.u64 %0, t; }" : "=r"(a) : "l"(p));
    return a;
}

#define LDSM4(r0, r1, r2, r3, addr) \
    asm volatile("ldmatrix.sync.aligned.m8n8.x4.shared.b16 {%0,%1,%2,%3},[%4];" \
        : "=r"(r0), "=r"(r1), "=r"(r2), "=r"(r3) : "r"(addr))

__device__ __forceinline__ void mma16816(float* d, u32 a0, u32 a1, u32 a2, u32 a3,
                                         u32 b0, u32 b1) {
    asm volatile(
        "mma.sync.aligned.m16n8k16.row.col.f32.bf16.bf16.f32 "
        "{%0,%1,%2,%3},{%4,%5,%6,%7},{%8,%9},{%0,%1,%2,%3};"
        : "+f"(d[0]), "+f"(d[1]), "+f"(d[2]), "+f"(d[3])
        : "r"(a0), "r"(a1), "r"(a2), "r"(a3), "r"(b0), "r"(b1));
}

__device__ __forceinline__ void split_store(unsigned char* dst_hi, unsigned char* dst_lo,
                                            float v0, float v1, float v2, float v3) {
    __nv_bfloat162 h01 = __floats2bfloat162_rn(v0, v1);
    __nv_bfloat162 h23 = __floats2bfloat162_rn(v2, v3);
    float l0 = v0 - __bfloat162float(h01.x);
    float l1 = v1 - __bfloat162float(h01.y);
    float l2 = v2 - __bfloat162float(h23.x);
    float l3 = v3 - __bfloat162float(h23.y);
    __nv_bfloat162 L01 = __floats2bfloat162_rn(l0, l1);
    __nv_bfloat162 L23 = __floats2bfloat162_rn(l2, l3);
    *(uint2*)dst_hi = make_uint2(*(u32*)&h01, *(u32*)&h23);
    *(uint2*)dst_lo = make_uint2(*(u32*)&L01, *(u32*)&L23);
}

// ============================================================
// Kernel 0: x NCHW -> NHWC
// ============================================================
__global__ void k_transpose_x(const float* __restrict__ x) {
    __shared__ float tile[64][129];
    int bh = blockIdx.x;
    int b = bh >> 7, h = bh & 127;
    int t = threadIdx.x;
    for (int i = t; i < 64 * 128; i += 256) {
        int c = i >> 7, w = i & 127;
        tile[c][w] = x[((size_t)(b * CC + c) * HH + h) * WW + w];
    }
    __syncthreads();
    for (int i = t; i < 64 * 128; i += 256) {
        int w = i >> 6, c = i & 63;
        g_xT[((size_t)bh * WW + w) * CC + c] = tile[c][w];
    }
}

// ============================================================
// Kernel 1: weight preps (R8)
// ============================================================
__global__ void k_prep_wb(const float* __restrict__ wgt) {
    int i = blockIdx.x * 256 + threadIdx.x;
    if (i >= NKK * OO * CC) return;
    int kk = i % 9;
    int c  = (i / 9) & 63;
    int o  = i / (9 * 64);
    float w = wgt[i];
    __nv_bfloat16 hi = __float2bfloat16(w);
    __nv_bfloat16 lo = __float2bfloat16(w - __bfloat162float(hi));
    g_wbH[(kk * OO + o) * CC + c] = hi;
    g_wbL[(kk * OO + o) * CC + c] = lo;
}

__global__ void k_prep_wpg(const float* __restrict__ pgw) {
    int i = blockIdx.x * 256 + threadIdx.x;     // 9*32*64
    if (i >= NKK * 32 * CC) return;
    int c  = i & 63;
    int co = (i >> 6) & 31;
    int kk = i >> 11;
    float w = (co < 27) ? pgw[co * QDIM + c * 9 + kk] : 0.f;
    __nv_bfloat16 hi = __float2bfloat16(w);
    __nv_bfloat16 lo = __float2bfloat16(w - __bfloat162float(hi));
    g_wpgH[i] = hi;
    g_wpgL[i] = lo;
}

// ============================================================
// MMA constants
// ============================================================
#define APITCH 72                    // bf16/row (144 B)
#define ROWB (APITCH*2)              // 144
#define A_BYTES (64 * ROWB)          // 9216
#define DPITCH 68

// ============================================================
// Kernel 2: offset/mask conv. block = 64 px, 256 thr (8 warps)
// warp = (pxg 0..3, ohalf 0..1). smem 27.6 KB (R8 layout)
// ============================================================
#define P_OFF_AH 0
#define P_OFF_AL (P_OFF_AH + A_BYTES)
#define P_OFF_BH (P_OFF_AL + A_BYTES)
#define P_OFF_BL (P_OFF_BH + 32 * ROWB)
#define P_SMEM   (P_OFF_BL + 32 * ROWB)               // 27648

__global__ void __launch_bounds__(256) k_params(const float* __restrict__ pgb) {
    __shared__ __align__(16) unsigned char blob[P_SMEM];
    u32 S = smem_u32(blob);
    int t = threadIdx.x;
    int lane = t & 31;
    int warp = t >> 5;               // 0..7
    int pxg = warp >> 1;
    int ohalf = warp & 1;
    int blk = blockIdx.x;            // 1024
    int wb = (blk & 1) * 64;
    int bh = blk >> 1;
    int b = bh >> 7, h = bh & 127;

    const float* xb = &g_xT[(size_t)b * HH * WW * CC];

    float acc[2][4];
#pragma unroll
    for (int j = 0; j < 2; j++)
#pragma unroll
        for (int r = 0; r < 4; r++) acc[j][r] = 0.f;

    u32 aRow = (u32)((pxg * 16 + (lane & 15)) * ROWB) + (u32)((lane >> 4) * 16);
    u32 bRowSel = (u32)(((lane & 7) + ((lane >> 4) & 1) * 8) * ROWB)
                  + (u32)(((lane >> 3) & 1) * 16);
    u32 bBase = (u32)(P_OFF_BH + ohalf * 16 * ROWB);
    int px = t >> 2;
    int q  = t & 3;                  // 16-c quarter

#pragma unroll 1
    for (int kk = 0; kk < NKK; kk++) {
        __syncthreads();             // prev MMA reads done
        // ---- stage A: shifted patch, this thread: (px, 16 c) ----
        {
            int dh = kk / 3 - 1, dw = kk % 3 - 1;
            int hh = h + dh;
            int gw = wb + px + dw;
            bool ok = (hh >= 0 && hh < HH && gw >= 0 && gw < WW);
            const float4* src = (const float4*)(xb +
                ((size_t)(ok ? hh : 0) * WW + (ok ? gw : 0)) * CC + q * 16);
            unsigned char* dh_ = blob + P_OFF_AH + px * ROWB + q * 32;
            unsigned char* dl_ = dh_ + A_BYTES;
#pragma unroll
            for (int i = 0; i < 4; i++) {
                float4 g = make_float4(0.f, 0.f, 0.f, 0.f);
                if (ok) g = __ldg(src + i);
                split_store(dh_ + i * 8, dl_ + i * 8, g.x, g.y, g.z, g.w);
            }
        }
        // ---- stage B: 32 co x 64 c (256 uint4 per buffer) ----
        {
            const uint4* gh = (const uint4*)&g_wpgH[(size_t)kk * 32 * CC];
            const uint4* gl = (const uint4*)&g_wpgL[(size_t)kk * 32 * CC];
            int row = t >> 3;
            int col = t & 7;
            *(uint4*)(blob + P_OFF_BH + row * ROWB + col * 16) = __ldg(&gh[t]);
            *(uint4*)(blob + P_OFF_BL + row * ROWB + col * 16) = __ldg(&gl[t]);
        }
        __syncthreads();
        // ---- MMA: this warp: 16 px x 16 co ----
#pragma unroll
        for (int ks = 0; ks < 4; ks++) {
            u32 aa = S + aRow + ks * 32;
            u32 ah0, ah1, ah2, ah3, al0, al1, al2, al3;
            LDSM4(ah0, ah1, ah2, ah3, aa);
            LDSM4(al0, al1, al2, al3, aa + A_BYTES);
            u32 ba = S + bBase + bRowSel + ks * 32;
            u32 bh0, bh1, bh2, bh3, bl0, bl1, bl2, bl3;
            LDSM4(bh0, bh1, bh2, bh3, ba);
            LDSM4(bl0, bl1, bl2, bl3, ba + 32 * ROWB);
            mma16816(acc[0], ah0, ah1, ah2, ah3, bh0, bh1);
            mma16816(acc[1], ah0, ah1, ah2, ah3, bh2, bh3);
            mma16816(acc[0], ah0, ah1, ah2, ah3, bl0, bl1);
            mma16816(acc[1], ah0, ah1, ah2, ah3, bl2, bl3);
            mma16816(acc[0], al0, al1, al2, al3, bh0, bh1);
            mma16816(acc[1], al0, al1, al2, al3, bh2, bh3);
        }
    }

    // ---- epilogue: stage sD[32co][68px], planar coalesced write ----
    __syncthreads();
    float* sD = (float*)blob;
    {
        int px0 = pxg * 16 + (lane >> 2);
#pragma unroll
        for (int j = 0; j < 2; j++) {
            int co = ohalf * 16 + j * 8 + 2 * (lane & 3);
            sD[co * DPITCH + px0]           = acc[j][0];
            sD[(co + 1) * DPITCH + px0]     = acc[j][1];
            sD[co * DPITCH + px0 + 8]       = acc[j][2];
            sD[(co + 1) * DPITCH + px0 + 8] = acc[j][3];
        }
    }
    __syncthreads();
#pragma unroll
    for (int i = 0; i < 7; i++) {
        int idx = i * 256 + t;               // 27*64 = 1728
        if (idx < 1728) {
            int co = idx >> 6;
            int pxx = idx & 63;
            g_params[(size_t)co * NPIX + (size_t)bh * WW + wb + pxx] =
                sD[co * DPITCH + pxx] + __ldg(&pgb[co]);
        }
    }
}

// ============================================================
// Kernel 3: fused gather + MMA. block = 64 px, 256 thr (8 warps)
// warp = (pxg 0..3, ohalf 0..1). smem 38.9 KB (R8 layout)
// ============================================================
#define OFF_AH 0
#define OFF_AL (OFF_AH + A_BYTES)
#define OFF_BH (OFF_AL + A_BYTES)
#define OFF_BL (OFF_BH + A_BYTES)
#define OFF_PW (OFF_BL + A_BYTES)            // float[4][64]
#define OFF_PI (OFF_PW + 4 * 64 * 4)         // int[4][64]
#define SMEM_BYTES (OFF_PI + 4 * 64 * 4)     // 38912

__global__ void __launch_bounds__(256) k_main(const float* __restrict__ bias,
                                              float* __restrict__ out) {
    __shared__ __align__(16) unsigned char blob[SMEM_BYTES];
    u32 S = smem_u32(blob);
    float* pw = (float*)(blob + OFF_PW);
    int*   pi = (int*)(blob + OFF_PI);

    int t = threadIdx.x;
    int lane = t & 31;
    int warp = t >> 5;               // 0..7
    int pxg = warp >> 1;
    int ohalf = warp & 1;
    int blk = blockIdx.x;
    int wb = (blk & 1) * 64;
    int bh = blk >> 1;
    int b = bh >> 7, h = bh & 127;

    const float* xb = &g_xT[(size_t)b * HH * WW * CC];

    float acc[4][4];                 // 4 n-tiles: o = ohalf*32 + (np*2+j)*8
#pragma unroll
    for (int j = 0; j < 4; j++)
#pragma unroll
        for (int r = 0; r < 4; r++) acc[j][r] = 0.f;

    u32 aRow = (u32)((pxg * 16 + (lane & 15)) * ROWB) + (u32)((lane >> 4) * 16);
    u32 bRowSel = (u32)(((lane & 7) + ((lane >> 4) & 1) * 8) * ROWB)
                  + (u32)(((lane >> 3) & 1) * 16);
    int px = t >> 2;
    int q  = t & 3;

#pragma unroll 1
    for (int kk = 0; kk < NKK; kk++) {
        __syncthreads();             // prev MMA reads done
        // ---- phase A: sampling params (threads 0..63) ----
        if (t < 64) {
            int pxp = t;
            int w = wb + pxp;
            size_t pixi = (size_t)bh * WW + w;
            float dy = __ldg(&g_params[(size_t)(2 * kk) * NPIX + pixi]);
            float dx = __ldg(&g_params[(size_t)(2 * kk + 1) * NPIX + pixi]);
            float m  = __ldg(&g_params[(size_t)(18 + kk) * NPIX + pixi]);
            float mask = 1.f / (1.f + expf(-m));
            float ys = (float)(h - 1 + kk / 3) + dy;
            float xs = (float)(w - 1 + kk % 3) + dx;
            float y0f = floorf(ys), x0f = floorf(xs);
            float ly = ys - y0f, lx = xs - x0f;
            int y0 = (int)y0f, x0 = (int)x0f;
            float vy0 = (y0 >= 0 && y0 < HH) ? 1.f : 0.f;
            float vy1 = (y0 + 1 >= 0 && y0 + 1 < HH) ? 1.f : 0.f;
            float vx0 = (x0 >= 0 && x0 < WW) ? 1.f : 0.f;
            float vx1 = (x0 + 1 >= 0 && x0 + 1 < WW) ? 1.f : 0.f;
            pw[0 * 64 + pxp] = (1.f - ly) * (1.f - lx) * mask * vy0 * vx0;
            pw[1 * 64 + pxp] = (1.f - ly) * lx         * mask * vy0 * vx1;
            pw[2 * 64 + pxp] = ly * (1.f - lx)         * mask * vy1 * vx0;
            pw[3 * 64 + pxp] = ly * lx                 * mask * vy1 * vx1;
            pi[0 * 64 + pxp] = min(max(y0, 0), HH - 1) * WW;
            pi[1 * 64 + pxp] = min(max(y0 + 1, 0), HH - 1) * WW;
            pi[2 * 64 + pxp] = min(max(x0, 0), WW - 1);
            pi[3 * 64 + pxp] = min(max(x0 + 1, 0), WW - 1);
        }
        // ---- stage B hi/lo: 64 o x 64 c (512 uint4 each) ----
        {
            const uint4* gh = (const uint4*)&g_wbH[(size_t)kk * OO * CC];
            const uint4* gl = (const uint4*)&g_wbL[(size_t)kk * OO * CC];
#pragma unroll
            for (int it = 0; it < 2; it++) {
                int idx = it * 256 + t;
                int row = idx >> 3;
                int col = idx & 7;
                *(uint4*)(blob + OFF_BH + row * ROWB + col * 16) = __ldg(&gh[idx]);
                *(uint4*)(blob + OFF_BL + row * ROWB + col * 16) = __ldg(&gl[idx]);
            }
        }
        __syncthreads();

        // ---- gather: this thread: (px, 16 c) ----
        {
            float w00 = pw[0 * 64 + px];
            float w01 = pw[1 * 64 + px];
            float w10 = pw[2 * 64 + px];
            float w11 = pw[3 * 64 + px];
            int r0  = pi[0 * 64 + px];
            int r1  = pi[1 * 64 + px];
            int x0c = pi[2 * 64 + px];
            int x1c = pi[3 * 64 + px];
            const float4* p00 = (const float4*)(xb + (size_t)(r0 + x0c) * CC + q * 16);
            const float4* p01 = (const float4*)(xb + (size_t)(r0 + x1c) * CC + q * 16);
            const float4* p10 = (const float4*)(xb + (size_t)(r1 + x0c) * CC + q * 16);
            const float4* p11 = (const float4*)(xb + (size_t)(r1 + x1c) * CC + q * 16);
            unsigned char* dh_ = blob + OFF_AH + px * ROWB + q * 32;
            unsigned char* dl_ = dh_ + A_BYTES;
#pragma unroll
            for (int i = 0; i < 4; i++) {
                float4 c0 = __ldg(p00 + i);
                float4 c1 = __ldg(p01 + i);
                float4 c2 = __ldg(p10 + i);
                float4 c3 = __ldg(p11 + i);
                float v0 = w00 * c0.x + w01 * c1.x + w10 * c2.x + w11 * c3.x;
                float v1 = w00 * c0.y + w01 * c1.y + w10 * c2.y + w11 * c3.y;
                float v2 = w00 * c0.z + w01 * c1.z + w10 * c2.z + w11 * c3.z;
                float v3 = w00 * c0.w + w01 * c1.w + w10 * c2.w + w11 * c3.w;
                split_store(dh_ + i * 8, dl_ + i * 8, v0, v1, v2, v3);
            }
        }
        __syncthreads();

        // ---- MMA: this warp: 16 px x 32 o ----
#pragma unroll
        for (int ks = 0; ks < 4; ks++) {
            u32 aa = S + aRow + ks * 32;
            u32 ah0, ah1, ah2, ah3, al0, al1, al2, al3;
            LDSM4(ah0, ah1, ah2, ah3, aa);
            LDSM4(al0, al1, al2, al3, aa + A_BYTES);
#pragma unroll
            for (int np = 0; np < 2; np++) {
                u32 ba = S + OFF_BH + (u32)((ohalf * 2 + np) * 16 * ROWB) + bRowSel + ks * 32;
                u32 bh0, bh1, bh2, bh3, bl0, bl1, bl2, bl3;
                LDSM4(bh0, bh1, bh2, bh3, ba);
                LDSM4(bl0, bl1, bl2, bl3, ba + A_BYTES);
                mma16816(acc[np * 2 + 0], ah0, ah1, ah2, ah3, bh0, bh1);
                mma16816(acc[np * 2 + 1], ah0, ah1, ah2, ah3, bh2, bh3);
                mma16816(acc[np * 2 + 0], ah0, ah1, ah2, ah3, bl0, bl1);
                mma16816(acc[np * 2 + 1], ah0, ah1, ah2, ah3, bl2, bl3);
                mma16816(acc[np * 2 + 0], al0, al1, al2, al3, bh0, bh1);
                mma16816(acc[np * 2 + 1], al0, al1, al2, al3, bh2, bh3);
            }
        }
    }

    // ---- epilogue ----
    __syncthreads();
    float* sD = (float*)blob;
    {
        int px0 = pxg * 16 + (lane >> 2);
#pragma unroll
        for (int j = 0; j < 4; j++) {
            int o = ohalf * 32 + j * 8 + 2 * (lane & 3);
            sD[o * DPITCH + px0]           = acc[j][0];
            sD[(o + 1) * DPITCH + px0]     = acc[j][1];
            sD[o * DPITCH + px0 + 8]       = acc[j][2];
            sD[(o + 1) * DPITCH + px0 + 8] = acc[j][3];
        }
    }
    __syncthreads();
    {
        int o = t >> 2;
        int qq = t & 3;
        float bv = __ldg(&bias[o]);
        size_t base = ((size_t)(b * OO + o) * HH + h) * WW + wb + qq * 16;
        const float* src = &sD[o * DPITCH + qq * 16];
#pragma unroll
        for (int i = 0; i < 4; i++) {
            float4 v = *(const float4*)&src[i * 4];
            v.x += bv; v.y += bv; v.z += bv; v.w += bv;
            *(float4*)&out[base + i * 4] = v;
        }
    }
}

// ============================================================
extern "C" void kernel_launch(void* const* d_in, const int* in_sizes, int n_in,
                              void* d_out, int out_size) {
    const float* x      = (const float*)d_in[0];
    const float* weight = (const float*)d_in[1];
    const float* bias   = (const float*)d_in[2];
    const float* pg_w   = (const float*)d_in[3];
    const float* pg_b   = (const float*)d_in[4];
    float* out = (float*)d_out;

    k_transpose_x<<<BB * HH, 256>>>(x);
    k_prep_wb<<<(NKK * OO * CC + 255) / 256, 256>>>(weight);
    k_prep_wpg<<<(NKK * 32 * CC + 255) / 256, 256>>>(pg_w);
    k_params<<<BB * HH * 2, 256>>>(pg_b);
    k_main<<<BB * HH * 2, 256>>>(bias, out);
}

// round 12
// speedup vs baseline: 2.5355x; 1.5095x over previous
#include <cuda_runtime.h>
#include <cuda_fp16.h>
#include <math.h>

#define BB 4
#define CC 64
#define HH 128
#define WW 128
#define OO 64
#define NKK 9
#define QDIM 576
#define NPIX (BB*HH*WW)     // 65536

typedef unsigned int u32;

// ---- device scratch ----
__device__ float g_xT[BB*HH*WW*CC];             // NHWC x
__device__ float g_params[27*NPIX];             // planar [co][pix]
__device__ __half g_wb[NKK*OO*CC];              // main weights fp16, [kk][o][c]
__device__ __half g_wpg[NKK*32*CC];             // pg weights fp16, [kk][co32][c]

__device__ __forceinline__ u32 smem_u32(const void* p) {
    u32 a;
    asm("{ .reg .u64 t; cvta.to.shared.u64 t, %1; cvt.u32.u64 %0, t; }" : "=r"(a) : "l"(p));
    return a;
}

#define LDSM4(r0, r1, r2, r3, addr) \
    asm volatile("ldmatrix.sync.aligned.m8n8.x4.shared.b16 {%0,%1,%2,%3},[%4];" \
        : "=r"(r0), "=r"(r1), "=r"(r2), "=r"(r3) : "r"(addr))

__device__ __forceinline__ void mma16816(float* d, u32 a0, u32 a1, u32 a2, u32 a3,
                                         u32 b0, u32 b1) {
    asm volatile(
        "mma.sync.aligned.m16n8k16.row.col.f32.f16.f16.f32 "
        "{%0,%1,%2,%3},{%4,%5,%6,%7},{%8,%9},{%0,%1,%2,%3};"
        : "+f"(d[0]), "+f"(d[1]), "+f"(d[2]), "+f"(d[3])
        : "r"(a0), "r"(a1), "r"(a2), "r"(a3), "r"(b0), "r"(b1));
}

__device__ __forceinline__ void h2_store(unsigned char* dst,
                                         float v0, float v1, float v2, float v3) {
    __half2 a = __floats2half2_rn(v0, v1);
    __half2 b = __floats2half2_rn(v2, v3);
    *(uint2*)dst = make_uint2(*(u32*)&a, *(u32*)&b);
}

// ============================================================
// Kernel 0: x NCHW -> NHWC
// ============================================================
__global__ void k_transpose_x(const float* __restrict__ x) {
    __shared__ float tile[64][129];
    int bh = blockIdx.x;
    int b = bh >> 7, h = bh & 127;
    int t = threadIdx.x;
    for (int i = t; i < 64 * 128; i += 256) {
        int c = i >> 7, w = i & 127;
        tile[c][w] = x[((size_t)(b * CC + c) * HH + h) * WW + w];
    }
    __syncthreads();
    for (int i = t; i < 64 * 128; i += 256) {
        int w = i >> 6, c = i & 63;
        g_xT[((size_t)bh * WW + w) * CC + c] = tile[c][w];
    }
}

// ============================================================
// Kernel 1: weight preps (fp16)
// ============================================================
__global__ void k_prep_wb(const float* __restrict__ wgt) {
    int i = blockIdx.x * 256 + threadIdx.x;
    if (i >= NKK * OO * CC) return;
    int kk = i % 9;
    int c  = (i / 9) & 63;
    int o  = i / (9 * 64);
    g_wb[(kk * OO + o) * CC + c] = __float2half(wgt[i]);
}

__global__ void k_prep_wpg(const float* __restrict__ pgw) {
    int i = blockIdx.x * 256 + threadIdx.x;     // 9*32*64
    if (i >= NKK * 32 * CC) return;
    int c  = i & 63;
    int co = (i >> 6) & 31;
    int kk = i >> 11;
    float w = (co < 27) ? pgw[co * QDIM + c * 9 + kk] : 0.f;
    g_wpg[i] = __float2half(w);
}

// ============================================================
// MMA constants
// ============================================================
#define APITCH 72                    // fp16/row (144 B)
#define ROWB (APITCH*2)              // 144
#define A_BYTES (64 * ROWB)          // 9216
#define DPITCH 68

// ============================================================
// Kernel 2: offset/mask conv. block = 64 px, 128 thr, fp16 1-pass
// smem: A@0 (9216), B@9216 (32*144=4608) -> 13824; epilogue sD 8704
// ============================================================
#define P_OFF_B 9216
#define P_SMEM  13824

__global__ void __launch_bounds__(128) k_params(const float* __restrict__ pgb) {
    __shared__ __align__(16) unsigned char blob[P_SMEM];
    u32 S = smem_u32(blob);
    int t = threadIdx.x;
    int lane = t & 31;
    int warp = t >> 5;
    int blk = blockIdx.x;            // 1024
    int wb = (blk & 1) * 64;
    int bh = blk >> 1;
    int b = bh >> 7, h = bh & 127;

    const float* xb = &g_xT[(size_t)b * HH * WW * CC];

    float acc[4][4];
#pragma unroll
    for (int j = 0; j < 4; j++)
#pragma unroll
        for (int r = 0; r < 4; r++) acc[j][r] = 0.f;

    u32 aRow = (u32)((warp * 16 + (lane & 15)) * ROWB) + (u32)((lane >> 4) * 16);
    u32 bRowSel = (u32)(((lane & 7) + ((lane >> 4) & 1) * 8) * ROWB)
                  + (u32)(((lane >> 3) & 1) * 16);

#pragma unroll 1
    for (int kk = 0; kk < NKK; kk++) {
        int dh = kk / 3 - 1, dw = kk % 3 - 1;
        int hh = h + dh;
        __syncthreads();             // prev MMA reads done
        // ---- stage A: shifted patch 64 px x 64 c, fp16 ----
#pragma unroll
        for (int it = 0; it < 8; it++) {
            int idx = it * 128 + t;
            int c4 = idx & 15;
            int px = idx >> 4;
            int gw = wb + px + dw;
            float4 g = make_float4(0.f, 0.f, 0.f, 0.f);
            if (hh >= 0 && hh < HH && gw >= 0 && gw < WW)
                g = __ldg((const float4*)&xb[((size_t)hh * WW + gw) * CC + c4 * 4]);
            h2_store(blob + px * ROWB + c4 * 8, g.x, g.y, g.z, g.w);
        }
        // ---- stage B: 32 co x 64 c fp16 (256 uint4) ----
        {
            const uint4* gh = (const uint4*)&g_wpg[(size_t)kk * 32 * CC];
#pragma unroll
            for (int it = 0; it < 2; it++) {
                int idx = it * 128 + t;
                int row = idx >> 3;
                int col = idx & 7;
                *(uint4*)(blob + P_OFF_B + row * ROWB + col * 16) = __ldg(&gh[idx]);
            }
        }
        __syncthreads();
        // ---- MMA: 4 ksteps x 2 n-pairs, 1 pass ----
#pragma unroll
        for (int ks = 0; ks < 4; ks++) {
            u32 aa = S + aRow + ks * 32;
            u32 a0, a1, a2, a3;
            LDSM4(a0, a1, a2, a3, aa);
#pragma unroll
            for (int np = 0; np < 2; np++) {
                u32 ba = S + P_OFF_B + (u32)(np * 16 * ROWB) + bRowSel + ks * 32;
                u32 b0, b1, b2, b3;
                LDSM4(b0, b1, b2, b3, ba);
                mma16816(acc[np * 2 + 0], a0, a1, a2, a3, b0, b1);
                mma16816(acc[np * 2 + 1], a0, a1, a2, a3, b2, b3);
            }
        }
    }

    // ---- epilogue: stage sD[32co][68px], planar coalesced write ----
    __syncthreads();
    float* sD = (float*)blob;
    {
        int px0 = warp * 16 + (lane >> 2);
#pragma unroll
        for (int j = 0; j < 4; j++) {
            int co = j * 8 + 2 * (lane & 3);
            sD[co * DPITCH + px0]           = acc[j][0];
            sD[(co + 1) * DPITCH + px0]     = acc[j][1];
            sD[co * DPITCH + px0 + 8]       = acc[j][2];
            sD[(co + 1) * DPITCH + px0 + 8] = acc[j][3];
        }
    }
    __syncthreads();
#pragma unroll
    for (int i = 0; i < 14; i++) {
        int idx = i * 128 + t;               // 27*64 = 1728
        if (idx < 1728) {
            int co = idx >> 6;
            int px = idx & 63;
            g_params[(size_t)co * NPIX + (size_t)bh * WW + wb + px] =
                sD[co * DPITCH + px] + __ldg(&pgb[co]);
        }
    }
}

// ============================================================
// Kernel 3: fused gather + MMA. block = 64 px, 128 thr, fp16 1-pass
// smem: A@0 (9216), B@9216 (9216), pw@18432 (1KB), pi@19456 (1KB) -> 20480
// ============================================================
#define M_OFF_B  9216
#define M_OFF_PW 18432
#define M_OFF_PI 19456
#define M_SMEM   20480

__global__ void __launch_bounds__(128) k_main(const float* __restrict__ bias,
                                              float* __restrict__ out) {
    __shared__ __align__(16) unsigned char blob[M_SMEM];
    u32 S = smem_u32(blob);
    float* pw = (float*)(blob + M_OFF_PW);
    int*   pi = (int*)(blob + M_OFF_PI);

    int t = threadIdx.x;
    int lane = t & 31;
    int warp = t >> 5;
    int blk = blockIdx.x;
    int wb = (blk & 1) * 64;
    int bh = blk >> 1;
    int b = bh >> 7, h = bh & 127;

    const float* xb = &g_xT[(size_t)b * HH * WW * CC];

    float acc[8][4];
#pragma unroll
    for (int j = 0; j < 8; j++)
#pragma unroll
        for (int r = 0; r < 4; r++) acc[j][r] = 0.f;

    u32 aRow = (u32)((warp * 16 + (lane & 15)) * ROWB) + (u32)((lane >> 4) * 16);
    u32 bRowSel = (u32)(((lane & 7) + ((lane >> 4) & 1) * 8) * ROWB)
                  + (u32)(((lane >> 3) & 1) * 16);

#pragma unroll 1
    for (int kk = 0; kk < NKK; kk++) {
        __syncthreads();             // prev MMA reads done
        // ---- phase A: sampling params (threads 0..63) ----
        if (t < 64) {
            int px = t;
            int w = wb + px;
            size_t pixi = (size_t)bh * WW + w;
            float dy = __ldg(&g_params[(size_t)(2 * kk) * NPIX + pixi]);
            float dx = __ldg(&g_params[(size_t)(2 * kk + 1) * NPIX + pixi]);
            float m  = __ldg(&g_params[(size_t)(18 + kk) * NPIX + pixi]);
            float mask = 1.f / (1.f + expf(-m));
            float ys = (float)(h - 1 + kk / 3) + dy;
            float xs = (float)(w - 1 + kk % 3) + dx;
            float y0f = floorf(ys), x0f = floorf(xs);
            float ly = ys - y0f, lx = xs - x0f;
            int y0 = (int)y0f, x0 = (int)x0f;
            float vy0 = (y0 >= 0 && y0 < HH) ? 1.f : 0.f;
            float vy1 = (y0 + 1 >= 0 && y0 + 1 < HH) ? 1.f : 0.f;
            float vx0 = (x0 >= 0 && x0 < WW) ? 1.f : 0.f;
            float vx1 = (x0 + 1 >= 0 && x0 + 1 < WW) ? 1.f : 0.f;
            pw[0 * 64 + px] = (1.f - ly) * (1.f - lx) * mask * vy0 * vx0;
            pw[1 * 64 + px] = (1.f - ly) * lx         * mask * vy0 * vx1;
            pw[2 * 64 + px] = ly * (1.f - lx)         * mask * vy1 * vx0;
            pw[3 * 64 + px] = ly * lx                 * mask * vy1 * vx1;
            pi[0 * 64 + px] = min(max(y0, 0), HH - 1) * WW;
            pi[1 * 64 + px] = min(max(y0 + 1, 0), HH - 1) * WW;
            pi[2 * 64 + px] = min(max(x0, 0), WW - 1);
            pi[3 * 64 + px] = min(max(x0 + 1, 0), WW - 1);
        }
        // ---- stage B: 64 o x 64 c fp16 (512 uint4) ----
        {
            const uint4* gh = (const uint4*)&g_wb[(size_t)kk * OO * CC];
#pragma unroll
            for (int it = 0; it < 4; it++) {
                int idx = it * 128 + t;
                int row = idx >> 3;
                int col = idx & 7;
                *(uint4*)(blob + M_OFF_B + row * ROWB + col * 16) = __ldg(&gh[idx]);
            }
        }
        __syncthreads();

        // ---- gather: 64 px x 16 c4, fp16 into A ----
#pragma unroll
        for (int it = 0; it < 8; it++) {
            int idx = it * 128 + t;
            int c4 = idx & 15;
            int px = idx >> 4;
            float w00 = pw[0 * 64 + px];
            float w01 = pw[1 * 64 + px];
            float w10 = pw[2 * 64 + px];
            float w11 = pw[3 * 64 + px];
            int r0  = pi[0 * 64 + px];
            int r1  = pi[1 * 64 + px];
            int x0c = pi[2 * 64 + px];
            int x1c = pi[3 * 64 + px];
            float4 g00 = __ldg((const float4*)&xb[(size_t)(r0 + x0c) * CC + c4 * 4]);
            float4 g01 = __ldg((const float4*)&xb[(size_t)(r0 + x1c) * CC + c4 * 4]);
            float4 g10 = __ldg((const float4*)&xb[(size_t)(r1 + x0c) * CC + c4 * 4]);
            float4 g11 = __ldg((const float4*)&xb[(size_t)(r1 + x1c) * CC + c4 * 4]);
            float v0 = w00 * g00.x + w01 * g01.x + w10 * g10.x + w11 * g11.x;
            float v1 = w00 * g00.y + w01 * g01.y + w10 * g10.y + w11 * g11.y;
            float v2 = w00 * g00.z + w01 * g01.z + w10 * g10.z + w11 * g11.z;
            float v3 = w00 * g00.w + w01 * g01.w + w10 * g10.w + w11 * g11.w;
            h2_store(blob + px * ROWB + c4 * 8, v0, v1, v2, v3);
        }
        __syncthreads();

        // ---- MMA: 4 ksteps x 4 n-pairs, 1 pass ----
#pragma unroll
        for (int ks = 0; ks < 4; ks++) {
            u32 aa = S + aRow + ks * 32;
            u32 a0, a1, a2, a3;
            LDSM4(a0, a1, a2, a3, aa);
#pragma unroll
            for (int np = 0; np < 4; np++) {
                u32 ba = S + M_OFF_B + (u32)(np * 16 * ROWB) + bRowSel + ks * 32;
                u32 b0, b1, b2, b3;
                LDSM4(b0, b1, b2, b3, ba);
                mma16816(acc[np * 2 + 0], a0, a1, a2, a3, b0, b1);
                mma16816(acc[np * 2 + 1], a0, a1, a2, a3, b2, b3);
            }
        }
    }

    // ---- epilogue: stage D in smem [o][px] (pitch 68), coalesced write ----
    __syncthreads();
    float* sD = (float*)blob;        // 64*68*4 = 17408 <= 20480
    {
        int px0 = warp * 16 + (lane >> 2);
#pragma unroll
        for (int j = 0; j < 8; j++) {
            int o = j * 8 + 2 * (lane & 3);
            sD[o * DPITCH + px0]           = acc[j][0];
            sD[(o + 1) * DPITCH + px0]     = acc[j][1];
            sD[o * DPITCH + px0 + 8]       = acc[j][2];
            sD[(o + 1) * DPITCH + px0 + 8] = acc[j][3];
        }
    }
    __syncthreads();
    {
        int o = t >> 1;
        int half = t & 1;
        float bv = __ldg(&bias[o]);
        size_t base = ((size_t)(b * OO + o) * HH + h) * WW + wb + half * 32;
        const float* src = &sD[o * DPITCH + half * 32];
#pragma unroll
        for (int i = 0; i < 8; i++) {
            float4 v = *(const float4*)&src[i * 4];
            v.x += bv; v.y += bv; v.z += bv; v.w += bv;
            *(float4*)&out[base + i * 4] = v;
        }
    }
}

// ============================================================
extern "C" void kernel_launch(void* const* d_in, const int* in_sizes, int n_in,
                              void* d_out, int out_size) {
    const float* x      = (const float*)d_in[0];
    const float* weight = (const float*)d_in[1];
    const float* bias   = (const float*)d_in[2];
    const float* pg_w   = (const float*)d_in[3];
    const float* pg_b   = (const float*)d_in[4];
    float* out = (float*)d_out;

    k_transpose_x<<<BB * HH, 256>>>(x);
    k_prep_wb<<<(NKK * OO * CC + 255) / 256, 256>>>(weight);
    k_prep_wpg<<<(NKK * 32 * CC + 255) / 256, 256>>>(pg_w);
    k_params<<<BB * HH * 2, 128>>>(pg_b);
    k_main<<<BB * HH * 2, 128>>>(bias, out);
}

// round 13
// speedup vs baseline: 3.2285x; 1.2733x over previous
#include <cuda_runtime.h>
#include <cuda_fp16.h>
#include <math.h>

#define BB 4
#define CC 64
#define HH 128
#define WW 128
#define OO 64
#define NKK 9
#define QDIM 576
#define NPIX (BB*HH*WW)     // 65536

typedef unsigned int u32;

// ---- device scratch ----
__device__ float g_xT[BB*HH*WW*CC];             // NHWC x
__device__ float g_params[27*NPIX];             // planar [co][pix]
__device__ __half g_wb[NKK*OO*CC];              // main weights fp16, [kk][o][c]
__device__ __half g_wpg[NKK*32*CC];             // pg weights fp16, [kk][co32][c]

__device__ __forceinline__ u32 smem_u32(const void* p) {
    u32 a;
    asm("{ .reg .u64 t; cvta.to.shared.u64 t, %1; cvt.u32.u64 %0, t; }" : "=r"(a) : "l"(p));
    return a;
}

#define LDSM4(r0, r1, r2, r3, addr) \
    asm volatile("ldmatrix.sync.aligned.m8n8.x4.shared.b16 {%0,%1,%2,%3},[%4];" \
        : "=r"(r0), "=r"(r1), "=r"(r2), "=r"(r3) : "r"(addr))

__device__ __forceinline__ void mma16816(float* d, u32 a0, u32 a1, u32 a2, u32 a3,
                                         u32 b0, u32 b1) {
    asm volatile(
        "mma.sync.aligned.m16n8k16.row.col.f32.f16.f16.f32 "
        "{%0,%1,%2,%3},{%4,%5,%6,%7},{%8,%9},{%0,%1,%2,%3};"
        : "+f"(d[0]), "+f"(d[1]), "+f"(d[2]), "+f"(d[3])
        : "r"(a0), "r"(a1), "r"(a2), "r"(a3), "r"(b0), "r"(b1));
}

__device__ __forceinline__ void h2_store(unsigned char* dst,
                                         float v0, float v1, float v2, float v3) {
    __half2 a = __floats2half2_rn(v0, v1);
    __half2 b = __floats2half2_rn(v2, v3);
    *(uint2*)dst = make_uint2(*(u32*)&a, *(u32*)&b);
}

// ============================================================
// Kernel 0: x NCHW -> NHWC
// ============================================================
__global__ void k_transpose_x(const float* __restrict__ x) {
    __shared__ float tile[64][129];
    int bh = blockIdx.x;
    int b = bh >> 7, h = bh & 127;
    int t = threadIdx.x;
    for (int i = t; i < 64 * 128; i += 256) {
        int c = i >> 7, w = i & 127;
        tile[c][w] = x[((size_t)(b * CC + c) * HH + h) * WW + w];
    }
    __syncthreads();
    for (int i = t; i < 64 * 128; i += 256) {
        int w = i >> 6, c = i & 63;
        g_xT[((size_t)bh * WW + w) * CC + c] = tile[c][w];
    }
}

// ============================================================
// Kernel 1: weight preps (fp16)
// ============================================================
__global__ void k_prep_wb(const float* __restrict__ wgt) {
    int i = blockIdx.x * 256 + threadIdx.x;
    if (i >= NKK * OO * CC) return;
    int kk = i % 9;
    int c  = (i / 9) & 63;
    int o  = i / (9 * 64);
    g_wb[(kk * OO + o) * CC + c] = __float2half(wgt[i]);
}

__global__ void k_prep_wpg(const float* __restrict__ pgw) {
    int i = blockIdx.x * 256 + threadIdx.x;     // 9*32*64
    if (i >= NKK * 32 * CC) return;
    int c  = i & 63;
    int co = (i >> 6) & 31;
    int kk = i >> 11;
    float w = (co < 27) ? pgw[co * QDIM + c * 9 + kk] : 0.f;
    g_wpg[i] = __float2half(w);
}

// ============================================================
// MMA constants
// ============================================================
#define APITCH 72                    // fp16/row (144 B)
#define ROWB (APITCH*2)              // 144
#define A_BYTES (64 * ROWB)          // 9216
#define DPITCH 68

// ============================================================
// Kernel 2: offset/mask conv. block = 64 px, 128 thr, fp16,
// double-buffered A pipeline (stage A(kk+1) overlaps MMA(kk))
// smem: A0@0, A1@9216, B@18432 (4608) -> 23040
// ============================================================
#define P_OFF_B 18432
#define P_SMEM  23040

__device__ __forceinline__ void p_stageA(unsigned char* blob, const float* xb,
                                         int t, int wb, int h, int kt, u32 aOff) {
    int dh = kt / 3 - 1, dw = kt % 3 - 1;
    int hh = h + dh;
#pragma unroll
    for (int it = 0; it < 8; it++) {
        int idx = it * 128 + t;
        int c4 = idx & 15;
        int px = idx >> 4;
        int gw = wb + px + dw;
        float4 g = make_float4(0.f, 0.f, 0.f, 0.f);
        if (hh >= 0 && hh < HH && gw >= 0 && gw < WW)
            g = __ldg((const float4*)&xb[((size_t)hh * WW + gw) * CC + c4 * 4]);
        h2_store(blob + aOff + px * ROWB + c4 * 8, g.x, g.y, g.z, g.w);
    }
}

__global__ void __launch_bounds__(128) k_params(const float* __restrict__ pgb) {
    __shared__ __align__(16) unsigned char blob[P_SMEM];
    u32 S = smem_u32(blob);
    int t = threadIdx.x;
    int lane = t & 31;
    int warp = t >> 5;
    int blk = blockIdx.x;            // 1024
    int wb = (blk & 1) * 64;
    int bh = blk >> 1;
    int b = bh >> 7, h = bh & 127;

    const float* xb = &g_xT[(size_t)b * HH * WW * CC];

    float acc[4][4];
#pragma unroll
    for (int j = 0; j < 4; j++)
#pragma unroll
        for (int r = 0; r < 4; r++) acc[j][r] = 0.f;

    u32 aRow = (u32)((warp * 16 + (lane & 15)) * ROWB) + (u32)((lane >> 4) * 16);
    u32 bRowSel = (u32)(((lane & 7) + ((lane >> 4) & 1) * 8) * ROWB)
                  + (u32)(((lane >> 3) & 1) * 16);

    // prologue: A for tap 0
    p_stageA(blob, xb, t, wb, h, 0, 0);

#pragma unroll 1
    for (int kk = 0; kk < NKK; kk++) {
        // ---- stage B(kk): 32 co x 64 c fp16 (256 uint4) ----
        {
            const uint4* gh = (const uint4*)&g_wpg[(size_t)kk * 32 * CC];
#pragma unroll
            for (int it = 0; it < 2; it++) {
                int idx = it * 128 + t;
                int row = idx >> 3;
                int col = idx & 7;
                *(uint4*)(blob + P_OFF_B + row * ROWB + col * 16) = __ldg(&gh[idx]);
            }
        }
        __syncthreads();             // A[kk&1], B(kk) visible
        // ---- stage A(kk+1) into alt buffer (overlaps MMA kk) ----
        if (kk < 8)
            p_stageA(blob, xb, t, wb, h, kk + 1, (u32)(((kk + 1) & 1) * A_BYTES));
        // ---- MMA(kk) ----
        u32 aBase = S + (u32)((kk & 1) * A_BYTES) + aRow;
#pragma unroll
        for (int ks = 0; ks < 4; ks++) {
            u32 aa = aBase + ks * 32;
            u32 a0, a1, a2, a3;
            LDSM4(a0, a1, a2, a3, aa);
#pragma unroll
            for (int np = 0; np < 2; np++) {
                u32 ba = S + P_OFF_B + (u32)(np * 16 * ROWB) + bRowSel + ks * 32;
                u32 b0, b1, b2, b3;
                LDSM4(b0, b1, b2, b3, ba);
                mma16816(acc[np * 2 + 0], a0, a1, a2, a3, b0, b1);
                mma16816(acc[np * 2 + 1], a0, a1, a2, a3, b2, b3);
            }
        }
        __syncthreads();             // MMA(kk) done before B(kk+1)/A reuse
    }

    // ---- epilogue: stage sD[32co][68px], planar coalesced write ----
    float* sD = (float*)blob;
    {
        int px0 = warp * 16 + (lane >> 2);
#pragma unroll
        for (int j = 0; j < 4; j++) {
            int co = j * 8 + 2 * (lane & 3);
            sD[co * DPITCH + px0]           = acc[j][0];
            sD[(co + 1) * DPITCH + px0]     = acc[j][1];
            sD[co * DPITCH + px0 + 8]       = acc[j][2];
            sD[(co + 1) * DPITCH + px0 + 8] = acc[j][3];
        }
    }
    __syncthreads();
#pragma unroll
    for (int i = 0; i < 14; i++) {
        int idx = i * 128 + t;               // 27*64 = 1728
        if (idx < 1728) {
            int co = idx >> 6;
            int px = idx & 63;
            g_params[(size_t)co * NPIX + (size_t)bh * WW + wb + px] =
                sD[co * DPITCH + px] + __ldg(&pgb[co]);
        }
    }
}

// ============================================================
// Kernel 3: fused gather + MMA. block = 64 px, 128 thr, fp16,
// double-buffered A + pw/pi slots; gather(kk+1) overlaps MMA(kk)
// smem: A0@0, A1@9216, B@18432 (9216), pw@27648 [2][4][64],
//       pi@29696 [2][4][64] -> 31744
// ============================================================
#define M_OFF_B  18432
#define M_OFF_PW 27648
#define M_OFF_PI 29696
#define M_SMEM   31744

__device__ __forceinline__ void m_params(unsigned char* blob, int t, int wb,
                                         int bh, int h, int kt, int slot) {
    if (t >= 64) return;
    float* pw = (float*)(blob + M_OFF_PW) + slot * 256;
    int*   pi = (int*)(blob + M_OFF_PI) + slot * 256;
    int px = t;
    int w = wb + px;
    size_t pixi = (size_t)bh * WW + w;
    float dy = __ldg(&g_params[(size_t)(2 * kt) * NPIX + pixi]);
    float dx = __ldg(&g_params[(size_t)(2 * kt + 1) * NPIX + pixi]);
    float m  = __ldg(&g_params[(size_t)(18 + kt) * NPIX + pixi]);
    float mask = 1.f / (1.f + expf(-m));
    float ys = (float)(h - 1 + kt / 3) + dy;
    float xs = (float)(w - 1 + kt % 3) + dx;
    float y0f = floorf(ys), x0f = floorf(xs);
    float ly = ys - y0f, lx = xs - x0f;
    int y0 = (int)y0f, x0 = (int)x0f;
    float vy0 = (y0 >= 0 && y0 < HH) ? 1.f : 0.f;
    float vy1 = (y0 + 1 >= 0 && y0 + 1 < HH) ? 1.f : 0.f;
    float vx0 = (x0 >= 0 && x0 < WW) ? 1.f : 0.f;
    float vx1 = (x0 + 1 >= 0 && x0 + 1 < WW) ? 1.f : 0.f;
    pw[0 * 64 + px] = (1.f - ly) * (1.f - lx) * mask * vy0 * vx0;
    pw[1 * 64 + px] = (1.f - ly) * lx         * mask * vy0 * vx1;
    pw[2 * 64 + px] = ly * (1.f - lx)         * mask * vy1 * vx0;
    pw[3 * 64 + px] = ly * lx                 * mask * vy1 * vx1;
    pi[0 * 64 + px] = min(max(y0, 0), HH - 1) * WW;
    pi[1 * 64 + px] = min(max(y0 + 1, 0), HH - 1) * WW;
    pi[2 * 64 + px] = min(max(x0, 0), WW - 1);
    pi[3 * 64 + px] = min(max(x0 + 1, 0), WW - 1);
}

__device__ __forceinline__ void m_gather(unsigned char* blob, const float* xb,
                                         int t, int slot, u32 aOff) {
    const float* pw = (const float*)(blob + M_OFF_PW) + slot * 256;
    const int*   pi = (const int*)(blob + M_OFF_PI) + slot * 256;
#pragma unroll
    for (int it = 0; it < 8; it++) {
        int idx = it * 128 + t;
        int c4 = idx & 15;
        int px = idx >> 4;
        float w00 = pw[0 * 64 + px];
        float w01 = pw[1 * 64 + px];
        float w10 = pw[2 * 64 + px];
        float w11 = pw[3 * 64 + px];
        int r0  = pi[0 * 64 + px];
        int r1  = pi[1 * 64 + px];
        int x0c = pi[2 * 64 + px];
        int x1c = pi[3 * 64 + px];
        float4 g00 = __ldg((const float4*)&xb[(size_t)(r0 + x0c) * CC + c4 * 4]);
        float4 g01 = __ldg((const float4*)&xb[(size_t)(r0 + x1c) * CC + c4 * 4]);
        float4 g10 = __ldg((const float4*)&xb[(size_t)(r1 + x0c) * CC + c4 * 4]);
        float4 g11 = __ldg((const float4*)&xb[(size_t)(r1 + x1c) * CC + c4 * 4]);
        float v0 = w00 * g00.x + w01 * g01.x + w10 * g10.x + w11 * g11.x;
        float v1 = w00 * g00.y + w01 * g01.y + w10 * g10.y + w11 * g11.y;
        float v2 = w00 * g00.z + w01 * g01.z + w10 * g10.z + w11 * g11.z;
        float v3 = w00 * g00.w + w01 * g01.w + w10 * g10.w + w11 * g11.w;
        h2_store(blob + aOff + px * ROWB + c4 * 8, v0, v1, v2, v3);
    }
}

__global__ void __launch_bounds__(128) k_main(const float* __restrict__ bias,
                                              float* __restrict__ out) {
    __shared__ __align__(16) unsigned char blob[M_SMEM];
    u32 S = smem_u32(blob);

    int t = threadIdx.x;
    int lane = t & 31;
    int warp = t >> 5;
    int blk = blockIdx.x;
    int wb = (blk & 1) * 64;
    int bh = blk >> 1;
    int b = bh >> 7, h = bh & 127;

    const float* xb = &g_xT[(size_t)b * HH * WW * CC];

    float acc[8][4];
#pragma unroll
    for (int j = 0; j < 8; j++)
#pragma unroll
        for (int r = 0; r < 4; r++) acc[j][r] = 0.f;

    u32 aRow = (u32)((warp * 16 + (lane & 15)) * ROWB) + (u32)((lane >> 4) * 16);
    u32 bRowSel = (u32)(((lane & 7) + ((lane >> 4) & 1) * 8) * ROWB)
                  + (u32)(((lane >> 3) & 1) * 16);

    // prologue: params(0) + gather(0) into A0
    m_params(blob, t, wb, bh, h, 0, 0);
    __syncthreads();
    m_gather(blob, xb, t, 0, 0);

#pragma unroll 1
    for (int kk = 0; kk < NKK; kk++) {
        // ---- stage B(kk): 64 o x 64 c fp16 (512 uint4) ----
        {
            const uint4* gh = (const uint4*)&g_wb[(size_t)kk * OO * CC];
#pragma unroll
            for (int it = 0; it < 4; it++) {
                int idx = it * 128 + t;
                int row = idx >> 3;
                int col = idx & 7;
                *(uint4*)(blob + M_OFF_B + row * ROWB + col * 16) = __ldg(&gh[idx]);
            }
        }
        // ---- params(kk+1) into alt slot ----
        if (kk < 8) m_params(blob, t, wb, bh, h, kk + 1, (kk + 1) & 1);
        __syncthreads();             // A[kk&1] (from prev iter), B(kk), params vis.
        // ---- gather(kk+1) into alt A buffer (LDGs lead; overlap MMA kk) ----
        if (kk < 8)
            m_gather(blob, xb, t, (kk + 1) & 1, (u32)(((kk + 1) & 1) * A_BYTES));
        // ---- MMA(kk) ----
        u32 aBase = S + (u32)((kk & 1) * A_BYTES) + aRow;
#pragma unroll
        for (int ks = 0; ks < 4; ks++) {
            u32 aa = aBase + ks * 32;
            u32 a0, a1, a2, a3;
            LDSM4(a0, a1, a2, a3, aa);
#pragma unroll
            for (int np = 0; np < 4; np++) {
                u32 ba = S + M_OFF_B + (u32)(np * 16 * ROWB) + bRowSel + ks * 32;
                u32 b0, b1, b2, b3;
                LDSM4(b0, b1, b2, b3, ba);
                mma16816(acc[np * 2 + 0], a0, a1, a2, a3, b0, b1);
                mma16816(acc[np * 2 + 1], a0, a1, a2, a3, b2, b3);
            }
        }
        __syncthreads();             // MMA(kk) + gather(kk+1) done
    }

    // ---- epilogue: stage D in smem [o][px] (pitch 68), coalesced write ----
    float* sD = (float*)blob;        // 64*68*4 = 17408 <= 31744
    {
        int px0 = warp * 16 + (lane >> 2);
#pragma unroll
        for (int j = 0; j < 8; j++) {
            int o = j * 8 + 2 * (lane & 3);
            sD[o * DPITCH + px0]           = acc[j][0];
            sD[(o + 1) * DPITCH + px0]     = acc[j][1];
            sD[o * DPITCH + px0 + 8]       = acc[j][2];
            sD[(o + 1) * DPITCH + px0 + 8] = acc[j][3];
        }
    }
    __syncthreads();
    {
        int o = t >> 1;
        int half = t & 1;
        float bv = __ldg(&bias[o]);
        size_t base = ((size_t)(b * OO + o) * HH + h) * WW + wb + half * 32;
        const float* src = &sD[o * DPITCH + half * 32];
#pragma unroll
        for (int i = 0; i < 8; i++) {
            float4 v = *(const float4*)&src[i * 4];
            v.x += bv; v.y += bv; v.z += bv; v.w += bv;
            *(float4*)&out[base + i * 4] = v;
        }
    }
}

// ============================================================
extern "C" void kernel_launch(void* const* d_in, const int* in_sizes, int n_in,
                              void* d_out, int out_size) {
    const float* x      = (const float*)d_in[0];
    const float* weight = (const float*)d_in[1];
    const float* bias   = (const float*)d_in[2];
    const float* pg_w   = (const float*)d_in[3];
    const float* pg_b   = (const float*)d_in[4];
    float* out = (float*)d_out;

    k_transpose_x<<<BB * HH, 256>>>(x);
    k_prep_wb<<<(NKK * OO * CC + 255) / 256, 256>>>(weight);
    k_prep_wpg<<<(NKK * 32 * CC + 255) / 256, 256>>>(pg_w);
    k_params<<<BB * HH * 2, 128>>>(pg_b);
    k_main<<<BB * HH * 2, 128>>>(bias, out);
}